// round 5
// baseline (speedup 1.0000x reference)
#include <cuda_runtime.h>
#include <stdint.h>

// GenerativeUpBlock: pruned generative transpose conv 3x3x3 stride 2.
// Inputs (metadata order):
//   d_in[0] in_feats     float32 [NP, 64]
//   d_in[1] weights      float32 [27, 64, 32]
//   d_in[2] bias         float32 [32]
//   d_in[3] in_coords    int [NP, 4]  (batch,x,y,z) even in [0,256)  -- int32 OR int64!
//   d_in[4] guide_coords int [NG, 4]  coords in [-1, 256]
// Output: float32 [NG, 32]

#define TABLE_SIZE (1 << 21)           // 128^3 dense stride-2 lattice
#define MAXG 400000
#define NOFF 27
#define GB 11                          // blocks per offset in compute kernel

__device__ __align__(16) int g_table[TABLE_SIZE];      // lin -> input row or -1
__device__ int               g_cnt[NOFF];              // per-offset pair counts
__device__ int               g_is64;                   // coord dtype flag
__device__ unsigned char     g_exists[MAXG];           // guide generated-set mask
__device__ int2              g_pairs[(size_t)NOFF * MAXG]; // (guide, input) per offset

// Read coord row r as (x,y,z), branching on detected dtype.
__device__ __forceinline__ void read_coord(const int* __restrict__ base, int r, int is64,
                                           int& x, int& y, int& z) {
    if (is64) {
        const long long* p = (const long long*)base;
        x = (int)p[(size_t)r * 4 + 1];
        y = (int)p[(size_t)r * 4 + 2];
        z = (int)p[(size_t)r * 4 + 3];
    } else {
        x = base[(size_t)r * 4 + 1];
        y = base[(size_t)r * 4 + 2];
        z = base[(size_t)r * 4 + 3];
    }
}

// ---------------------------------------------------------------------------
// Kernel 0: dtype probe. For little-endian int64 with non-negative values
// < 2^31 (true for in_coords: even, in [0,254]), every odd int32 half-word is
// zero. For int32 layout, odd slots hold x/z coordinates (random, mostly
// nonzero). 32 probes make a false positive essentially impossible.
// ---------------------------------------------------------------------------
__global__ void k_detect(const int* __restrict__ ic) {
    int allzero = 1;
    for (int j = 1; j < 64; j += 2)
        if (ic[j] != 0) allzero = 0;
    g_is64 = allzero;
}

// ---------------------------------------------------------------------------
// Kernel 1: reset table + counters (graph replays: must reset every launch)
// ---------------------------------------------------------------------------
__global__ void k_init() {
    int i = blockIdx.x * blockDim.x + threadIdx.x;
    for (int j = i; j < TABLE_SIZE; j += gridDim.x * blockDim.x)
        g_table[j] = -1;
    if (i < NOFF) g_cnt[i] = 0;
}

// ---------------------------------------------------------------------------
// Kernel 2: scatter input rows into dense table
// ---------------------------------------------------------------------------
__global__ void k_scatter(const int* __restrict__ ic, int np) {
    int i = blockIdx.x * blockDim.x + threadIdx.x;
    if (i >= np) return;
    int x, y, z;
    read_coord(ic, i, g_is64, x, y, z);
    if ((unsigned)x > 255u || (unsigned)y > 255u || (unsigned)z > 255u) return;
    if ((x | y | z) & 1) return;                       // inputs are even-lattice
    int lin = (x >> 1) | ((y >> 1) << 7) | ((z >> 1) << 14);
    g_table[lin] = i;
}

// ---------------------------------------------------------------------------
// Kernel 3: per guide point, test all 27 offsets.
// Offset o = (dx+1)*9 + (dy+1)*3 + (dz+1); contribution comes from p = q - d.
// p must be even per axis and inside [0,254] to possibly exist.
// ---------------------------------------------------------------------------
__global__ void k_match(const int* __restrict__ gc, int ng) {
    int g = blockIdx.x * blockDim.x + threadIdx.x;
    if (g >= ng) return;

    int qx, qy, qz;
    read_coord(gc, g, g_is64, qx, qy, qz);

    int nm = 0;
#pragma unroll
    for (int o = 0; o < NOFF; o++) {
        int dx = o / 9 - 1;
        int dy = (o / 3) % 3 - 1;
        int dz = o % 3 - 1;
        int px = qx - dx, py = qy - dy, pz = qz - dz;
        if ((px | py | pz) & 1) continue;                       // p must be even
        if ((unsigned)px > 254u || (unsigned)py > 254u || (unsigned)pz > 254u) continue;
        int lin = (px >> 1) | ((py >> 1) << 7) | ((pz >> 1) << 14);
        int idx = g_table[lin];
        if (idx >= 0) {
            int pos = atomicAdd(&g_cnt[o], 1);
            if (pos < MAXG)
                g_pairs[(size_t)o * MAXG + pos] = make_int2(g, idx);
            nm++;
        }
    }
    g_exists[g] = nm ? 1 : 0;
}

// ---------------------------------------------------------------------------
// Kernel 4: initialize output: bias where generated, zero elsewhere.
// ---------------------------------------------------------------------------
__global__ void k_outinit(const float* __restrict__ bias, float* __restrict__ out, int ng) {
    int e = blockIdx.x * blockDim.x + threadIdx.x;
    if (e >= ng * 32) return;
    int g = e >> 5;
    int c = e & 31;
    out[e] = g_exists[g] ? __ldg(&bias[c]) : 0.0f;
}

// ---------------------------------------------------------------------------
// Kernel 5: per-offset gather-GEMV. Block owns one offset; each lane holds one
// output column of W[o] in registers (64 regs). Feature row staged in a
// per-warp float4 smem buffer (alias-clean, double-buffered) and read back
// via conflict-free float4 broadcasts.
// ---------------------------------------------------------------------------
__global__ void __launch_bounds__(256) k_compute(const float* __restrict__ feats,
                                                 const float* __restrict__ W,
                                                 float* __restrict__ out) {
    const int o     = blockIdx.x % NOFF;
    const int chunk = blockIdx.x / NOFF;
    const int lane  = threadIdx.x & 31;
    const int warp  = threadIdx.x >> 5;

    __shared__ float4 sbuf[8][2][16];   // [warp][double-buffer][16 x float4 = 64 floats]

    // W[o][k][lane], k = 0..63 -> registers (one output column per lane)
    float wreg[64];
    const float* wp = W + o * (64 * 32) + lane;
#pragma unroll
    for (int k = 0; k < 64; k++) wreg[k] = __ldg(&wp[k * 32]);

    const int n   = g_cnt[o];
    const int wid = chunk * 8 + warp;
    const int nw  = GB * 8;

    int buf = 0;
    for (int p = wid; p < n; p += nw) {
        int2 pr = g_pairs[(size_t)o * MAXG + p];

        float4 v16;
        if (lane < 16) {
            const float4* fr4 = reinterpret_cast<const float4*>(feats + (size_t)pr.y * 64);
            v16 = __ldg(&fr4[lane]);
        }
        __syncwarp();                      // prior iteration's reads done
        if (lane < 16) sbuf[warp][buf][lane] = v16;
        __syncwarp();                      // stores visible to all lanes

        float a0 = 0.f, a1 = 0.f, a2 = 0.f, a3 = 0.f;
#pragma unroll
        for (int k = 0; k < 16; k++) {
            float4 v = sbuf[warp][buf][k]; // broadcast: all lanes same address
            a0 = fmaf(v.x, wreg[4 * k + 0], a0);
            a1 = fmaf(v.y, wreg[4 * k + 1], a1);
            a2 = fmaf(v.z, wreg[4 * k + 2], a2);
            a3 = fmaf(v.w, wreg[4 * k + 3], a3);
        }
        atomicAdd(&out[(size_t)pr.x * 32 + lane], (a0 + a1) + (a2 + a3));
        buf ^= 1;
    }
}

// ---------------------------------------------------------------------------
extern "C" void kernel_launch(void* const* d_in, const int* in_sizes, int n_in,
                              void* d_out, int out_size) {
    const float* feats = (const float*)d_in[0];
    const float* W     = (const float*)d_in[1];
    const float* bias  = (const float*)d_in[2];
    const int*   ic    = (const int*)d_in[3];
    const int*   gc    = (const int*)d_in[4];
    float*       out   = (float*)d_out;

    int np = in_sizes[0] / 64;   // in_feats elements / 64
    int ng = in_sizes[4] / 4;    // guide_coords elements / 4 (rows; dtype-independent)
    if (ng > MAXG) ng = MAXG;

    k_detect<<<1, 1>>>(ic);
    k_init<<<1024, 256>>>();
    k_scatter<<<(np + 255) / 256, 256>>>(ic, np);
    k_match<<<(ng + 255) / 256, 256>>>(gc, ng);
    k_outinit<<<(ng * 32 + 255) / 256, 256>>>(bias, out, ng);
    k_compute<<<NOFF * GB, 256>>>(feats, W, out);
}

// round 7
// speedup vs baseline: 1.6189x; 1.6189x over previous
#include <cuda_runtime.h>
#include <stdint.h>

// GenerativeUpBlock: pruned generative transpose conv 3x3x3 stride 2.
// Inputs (metadata order):
//   d_in[0] in_feats     float32 [NP, 64]
//   d_in[1] weights      float32 [27, 64, 32]
//   d_in[2] bias         float32 [32]
//   d_in[3] in_coords    [NP, 4]  (batch,x,y,z) even in [0,256)  -- int32 OR int64
//   d_in[4] guide_coords [NG, 4]  coords in [-1, 256]
// Output: float32 [NG, 32]

#define TABLE_SIZE (1 << 21)           // 128^3 dense stride-2 lattice
#define MAXG 400000
#define NOFF 27
#define GB 11                          // blocks per offset in compute kernel

__device__ __align__(16) int g_table[TABLE_SIZE];      // lin -> input row or -1
__device__ int               g_cnt[NOFF];              // per-offset pair counts
__device__ int               g_is64;                   // coord dtype flag
__device__ unsigned char     g_exists[MAXG];           // guide generated-set mask
__device__ int2              g_pairs[(size_t)NOFF * MAXG]; // (guide, input) per offset

// Read coord row r as (x,y,z), branching on detected dtype. Vector loads.
// int64 rows are 32 bytes: two int4 loads; x/y/z low words at int offsets 2/4/6
// (values are in [-1, 256] -> low word is the value for non-negatives; coords
// used here are validated by range checks immediately after anyway).
__device__ __forceinline__ void read_coord(const int* __restrict__ base, int r, int is64,
                                           int& x, int& y, int& z) {
    const int4* p = (const int4*)base;
    if (is64) {
        int4 lo = __ldg(&p[2 * r]);        // ints 0..3 of the row
        int4 hi = __ldg(&p[2 * r + 1]);    // ints 4..7
        x = lo.z; y = hi.x; z = hi.z;
    } else {
        int4 v = __ldg(&p[r]);
        x = v.y; y = v.z; z = v.w;
    }
}

// ---------------------------------------------------------------------------
// Kernel 0: dtype probe (1 warp). For LE int64 with values in [0, 2^31),
// every odd int32 slot is zero; for int32 layout odd slots hold coords.
// ---------------------------------------------------------------------------
__global__ void k_detect(const int* __restrict__ ic) {
    int lane = threadIdx.x;
    int nz = (ic[2 * lane + 1] != 0);          // probe odd slots 1,3,...,63
    unsigned any = __ballot_sync(0xffffffffu, nz);
    if (lane == 0) g_is64 = (any == 0u);
}

// ---------------------------------------------------------------------------
// Kernel 1: reset table + counters (graph replays: must reset every launch)
// ---------------------------------------------------------------------------
__global__ void k_init() {
    int i = blockIdx.x * blockDim.x + threadIdx.x;
    for (int j = i; j < TABLE_SIZE; j += gridDim.x * blockDim.x)
        g_table[j] = -1;
    if (i < NOFF) g_cnt[i] = 0;
}

// ---------------------------------------------------------------------------
// Kernel 2: scatter input rows into dense table
// ---------------------------------------------------------------------------
__global__ void k_scatter(const int* __restrict__ ic, int np) {
    int i = blockIdx.x * blockDim.x + threadIdx.x;
    if (i >= np) return;
    int x, y, z;
    read_coord(ic, i, g_is64, x, y, z);
    if ((unsigned)x > 255u || (unsigned)y > 255u || (unsigned)z > 255u) return;
    if ((x | y | z) & 1) return;                       // inputs are even-lattice
    int lin = (x >> 1) | ((y >> 1) << 7) | ((z >> 1) << 14);
    g_table[lin] = i;
}

// ---------------------------------------------------------------------------
// Kernel 3: per guide point, test parity-valid offsets (<=8); emit pairs into
// per-offset segments with BLOCK-AGGREGATED atomics: smem counters per offset,
// one global atomicAdd per (block, offset), then scattered writes.
// Offset o = (dx+1)*9 + (dy+1)*3 + (dz+1); contribution from p = q - d,
// which must be even per axis and inside [0,254].
// ---------------------------------------------------------------------------
__global__ void k_match(const int* __restrict__ gc, int ng) {
    __shared__ int scnt[NOFF];
    __shared__ int sbase[NOFF];
    const int tid = threadIdx.x;
    if (tid < NOFF) scnt[tid] = 0;
    __syncthreads();

    const int g = blockIdx.x * blockDim.x + tid;
    int nm = 0;
    int mo[8], mi[8], mslot[8];

    if (g < ng) {
        int qx, qy, qz;
        read_coord(gc, g, g_is64, qx, qy, qz);
        int ox = qx & 1, oy = qy & 1, oz = qz & 1;   // odd axis => d in {-1,1}; even => {0}
        int ndx = ox ? 2 : 1, ndy = oy ? 2 : 1, ndz = oz ? 2 : 1;

        for (int a = 0; a < ndx; a++) {
            int dx = ox ? (a * 2 - 1) : 0;
            int px = qx - dx;
            if ((unsigned)px > 254u) continue;
            for (int b = 0; b < ndy; b++) {
                int dy = oy ? (b * 2 - 1) : 0;
                int py = qy - dy;
                if ((unsigned)py > 254u) continue;
                for (int c = 0; c < ndz; c++) {
                    int dz = oz ? (c * 2 - 1) : 0;
                    int pz = qz - dz;
                    if ((unsigned)pz > 254u) continue;
                    int lin = (px >> 1) | ((py >> 1) << 7) | ((pz >> 1) << 14);
                    int idx = g_table[lin];
                    if (idx >= 0) {
                        mo[nm] = (dx + 1) * 9 + (dy + 1) * 3 + (dz + 1);
                        mi[nm] = idx;
                        nm++;
                    }
                }
            }
        }
        g_exists[g] = nm ? 1 : 0;
    }

    for (int m = 0; m < nm; m++) mslot[m] = atomicAdd(&scnt[mo[m]], 1);
    __syncthreads();
    if (tid < NOFF && scnt[tid] > 0) sbase[tid] = atomicAdd(&g_cnt[tid], scnt[tid]);
    __syncthreads();
    for (int m = 0; m < nm; m++) {
        int o = mo[m];
        g_pairs[(size_t)o * MAXG + sbase[o] + mslot[m]] = make_int2(g, mi[m]);
    }
}

// ---------------------------------------------------------------------------
// Kernel 4: initialize output: bias where generated, zero elsewhere.
// ---------------------------------------------------------------------------
__global__ void k_outinit(const float* __restrict__ bias, float* __restrict__ out, int ng) {
    int e = blockIdx.x * blockDim.x + threadIdx.x;
    if (e >= ng * 32) return;
    int g = e >> 5;
    int c = e & 31;
    out[e] = g_exists[g] ? __ldg(&bias[c]) : 0.0f;
}

// ---------------------------------------------------------------------------
// Kernel 5: per-offset gather-GEMV. Block owns one offset; each lane holds one
// output column of W[o] in registers (64 regs). Feature row staged in a
// per-warp float4 smem buffer (double-buffered) and read back via
// conflict-free float4 broadcasts.
// ---------------------------------------------------------------------------
__global__ void __launch_bounds__(256) k_compute(const float* __restrict__ feats,
                                                 const float* __restrict__ W,
                                                 float* __restrict__ out) {
    const int o     = blockIdx.x % NOFF;
    const int chunk = blockIdx.x / NOFF;
    const int lane  = threadIdx.x & 31;
    const int warp  = threadIdx.x >> 5;

    __shared__ float4 sbuf[8][2][16];   // [warp][double-buffer][16 x float4 = 64 floats]

    // W[o][k][lane], k = 0..63 -> registers (one output column per lane)
    float wreg[64];
    const float* wp = W + o * (64 * 32) + lane;
#pragma unroll
    for (int k = 0; k < 64; k++) wreg[k] = __ldg(&wp[k * 32]);

    const int n   = g_cnt[o];
    const int wid = chunk * 8 + warp;
    const int nw  = GB * 8;

    int buf = 0;
    for (int p = wid; p < n; p += nw) {
        int2 pr = g_pairs[(size_t)o * MAXG + p];

        float4 v16;
        if (lane < 16) {
            const float4* fr4 = reinterpret_cast<const float4*>(feats + (size_t)pr.y * 64);
            v16 = __ldg(&fr4[lane]);
        }
        __syncwarp();                      // prior iteration's reads done
        if (lane < 16) sbuf[warp][buf][lane] = v16;
        __syncwarp();                      // stores visible to all lanes

        float a0 = 0.f, a1 = 0.f, a2 = 0.f, a3 = 0.f;
#pragma unroll
        for (int k = 0; k < 16; k++) {
            float4 v = sbuf[warp][buf][k]; // broadcast: all lanes same address
            a0 = fmaf(v.x, wreg[4 * k + 0], a0);
            a1 = fmaf(v.y, wreg[4 * k + 1], a1);
            a2 = fmaf(v.z, wreg[4 * k + 2], a2);
            a3 = fmaf(v.w, wreg[4 * k + 3], a3);
        }
        atomicAdd(&out[(size_t)pr.x * 32 + lane], (a0 + a1) + (a2 + a3));
        buf ^= 1;
    }
}

// ---------------------------------------------------------------------------
extern "C" void kernel_launch(void* const* d_in, const int* in_sizes, int n_in,
                              void* d_out, int out_size) {
    const float* feats = (const float*)d_in[0];
    const float* W     = (const float*)d_in[1];
    const float* bias  = (const float*)d_in[2];
    const int*   ic    = (const int*)d_in[3];
    const int*   gc    = (const int*)d_in[4];
    float*       out   = (float*)d_out;

    int np = in_sizes[0] / 64;   // in_feats elements / 64
    int ng = in_sizes[4] / 4;    // guide_coords rows (dtype-independent)
    if (ng > MAXG) ng = MAXG;

    k_detect<<<1, 32>>>(ic);
    k_init<<<1024, 256>>>();
    k_scatter<<<(np + 255) / 256, 256>>>(ic, np);
    k_match<<<(ng + 255) / 256, 256>>>(gc, ng);
    k_outinit<<<(ng * 32 + 255) / 256, 256>>>(bias, out, ng);
    k_compute<<<NOFF * GB, 256>>>(feats, W, out);
}